// round 3
// baseline (speedup 1.0000x reference)
#include <cuda_runtime.h>
#include <math.h>
#include <stdint.h>

#define BB 8
#define TT 2048
#define HH 1024
#define DD 64
#define NTOK (BB*TT)   // 16384

// scratch for projected q,k,v (values pre-rounded to tf32, stored as fp32 bits)
__device__ float g_q[NTOK*DD];
__device__ float g_k[NTOK*DD];
__device__ float g_v[NTOK*DD];

// ---------------------------------------------------------------------------
// helpers
// ---------------------------------------------------------------------------
__device__ __forceinline__ uint32_t f2tf(float f) {
    uint32_t r; asm("cvt.rna.tf32.f32 %0, %1;" : "=r"(r) : "f"(f)); return r;
}

__device__ __forceinline__ void mma8(float c[4],
    uint32_t a0, uint32_t a1, uint32_t a2, uint32_t a3,
    uint32_t b0, uint32_t b1)
{
    asm volatile(
        "mma.sync.aligned.m16n8k8.row.col.f32.tf32.tf32.f32 "
        "{%0,%1,%2,%3}, {%4,%5,%6,%7}, {%8,%9}, {%0,%1,%2,%3};"
        : "+f"(c[0]), "+f"(c[1]), "+f"(c[2]), "+f"(c[3])
        : "r"(a0), "r"(a1), "r"(a2), "r"(a3), "r"(b0), "r"(b1));
}

__device__ __forceinline__ void groupbar(int id) {
    asm volatile("bar.sync %0, %1;" :: "r"(id), "r"(128));
}

// column permutation: puts logical cols (c, c+4) adjacent -> 64-bit frag loads
__device__ __forceinline__ int perm8(int c) {
    return (c & ~7) | ((c & 3) << 1) | ((c >> 2) & 1);
}

// 64-col arrays (attn): scalar store index / uint2 frag load, XOR swizzle
__device__ __forceinline__ int swz64(int r, int c /*permuted col*/) {
    int c2 = c >> 1;
    return r * 64 + (((c2 ^ ((r & 3) << 2)) << 1) | (c & 1));
}
__device__ __forceinline__ uint2 ld64(const uint32_t* a, int r, int c2) {
    return ((const uint2*)a)[r * 32 + (c2 ^ ((r & 3) << 2))];
}

// 32-col arrays (proj)
__device__ __forceinline__ int swz32(int r, int c) {
    int c2 = c >> 1;
    return r * 32 + (((c2 ^ ((r & 3) << 2)) << 1) | (c & 1));
}
__device__ __forceinline__ uint2 ld32(const uint32_t* a, int r, int c2) {
    return ((const uint2*)a)[r * 16 + (c2 ^ ((r & 3) << 2))];
}

// ---------------------------------------------------------------------------
// Fused projection: y = x @ [Wq|Wk|Wv], M=16384, N=192, K=1024, tf32 mma.
// Block tile M=128, N=192, k-chunk 32, DOUBLE-BUFFERED smem with reg staging.
// 512 threads = 16 warps (4m x 4n), warp tile 32x48.
// Outputs are rounded to tf32 before storing (attn consumes raw bits).
// ---------------------------------------------------------------------------
#define PROJ_SMEM (20480 * 4)   // xs[2][4096] + wt[2][6144] uint32

__device__ __forceinline__ void proj_ldg(
    const float* __restrict__ x,
    const float* __restrict__ Wq, const float* __restrict__ Wk,
    const float* __restrict__ Wv,
    int row0, int k0, int t, float4 xr[2], float4 wlo[2], float4 whi[2])
{
    #pragma unroll
    for (int i = 0; i < 2; i++) {
        int f4 = t + i * 512;
        int r = f4 >> 3, c0 = (f4 & 7) * 4;
        xr[i] = *(const float4*)&x[(size_t)(row0 + r) * HH + k0 + c0];
    }
    #pragma unroll
    for (int i = 0; i < 2; i++) {
        int tau = t + i * 512;
        if (tau < 768) {
            int kp = tau & 15, n4 = tau >> 4;
            int k  = ((kp >> 2) << 3) | (kp & 3);
            int n0 = n4 * 4;
            const float* W = (n0 < 64) ? Wq : (n0 < 128) ? Wk : Wv;
            int ncol = n0 & 63;
            wlo[i] = *(const float4*)&W[(size_t)(k0 + k)     * DD + ncol];
            whi[i] = *(const float4*)&W[(size_t)(k0 + k + 4) * DD + ncol];
        }
    }
}

__device__ __forceinline__ void proj_sts(
    uint32_t* xs, uint32_t* wt, int t,
    const float4 xr[2], const float4 wlo[2], const float4 whi[2])
{
    #pragma unroll
    for (int i = 0; i < 2; i++) {
        int f4 = t + i * 512;
        int r = f4 >> 3, c0 = (f4 & 7) * 4;
        xs[swz32(r, perm8(c0 + 0))] = f2tf(xr[i].x);
        xs[swz32(r, perm8(c0 + 1))] = f2tf(xr[i].y);
        xs[swz32(r, perm8(c0 + 2))] = f2tf(xr[i].z);
        xs[swz32(r, perm8(c0 + 3))] = f2tf(xr[i].w);
    }
    #pragma unroll
    for (int i = 0; i < 2; i++) {
        int tau = t + i * 512;
        if (tau < 768) {
            int kp = tau & 15, n4 = tau >> 4;
            int k  = ((kp >> 2) << 3) | (kp & 3);
            int n0 = n4 * 4;
            int col2 = ((k & ~7) >> 1) | (k & 3);
            uint2* w2 = (uint2*)wt;
            w2[(n0 + 0) * 16 + (col2 ^ 0)]  = make_uint2(f2tf(wlo[i].x), f2tf(whi[i].x));
            w2[(n0 + 1) * 16 + (col2 ^ 4)]  = make_uint2(f2tf(wlo[i].y), f2tf(whi[i].y));
            w2[(n0 + 2) * 16 + (col2 ^ 8)]  = make_uint2(f2tf(wlo[i].z), f2tf(whi[i].z));
            w2[(n0 + 3) * 16 + (col2 ^ 12)] = make_uint2(f2tf(wlo[i].w), f2tf(whi[i].w));
        }
    }
}

__global__ __launch_bounds__(512) void proj_kernel(
    const float* __restrict__ x,
    const float* __restrict__ Wk,
    const float* __restrict__ Wq,
    const float* __restrict__ Wv)
{
    extern __shared__ uint32_t psm[];
    // layout: xs0[0,4096) xs1[4096,8192) wt0[8192,14336) wt1[14336,20480)

    const int t    = threadIdx.x;
    const int lane = t & 31;
    const int warp = t >> 5;
    const int g    = lane >> 2;
    const int tig  = lane & 3;
    const int warpM = warp >> 2;
    const int warpN = warp & 3;
    const int row0 = blockIdx.x * 128;

    float acc[2][6][4];
    #pragma unroll
    for (int a = 0; a < 2; a++)
        #pragma unroll
        for (int j = 0; j < 6; j++)
            #pragma unroll
            for (int e = 0; e < 4; e++) acc[a][j][e] = 0.f;

    float4 xr[2], wlo[2], whi[2];
    proj_ldg(x, Wq, Wk, Wv, row0, 0, t, xr, wlo, whi);
    proj_sts(psm, psm + 8192, t, xr, wlo, whi);
    __syncthreads();

    for (int c = 0; c < 32; c++) {
        if (c + 1 < 32)
            proj_ldg(x, Wq, Wk, Wv, row0, (c + 1) * 32, t, xr, wlo, whi);

        const uint32_t* xsb = psm + (c & 1) * 4096;
        const uint32_t* wtb = psm + 8192 + (c & 1) * 6144;

        #pragma unroll
        for (int ks = 0; ks < 4; ks++) {
            int c2 = ks * 4 + tig;
            int rA = warpM * 32 + g;
            uint2 A02_0 = ld32(xsb, rA,      c2);
            uint2 A13_0 = ld32(xsb, rA + 8,  c2);
            uint2 A02_1 = ld32(xsb, rA + 16, c2);
            uint2 A13_1 = ld32(xsb, rA + 24, c2);
            #pragma unroll
            for (int j = 0; j < 6; j++) {
                int n = warpN * 48 + j * 8 + g;
                uint2 B = ld32(wtb, n, c2);
                mma8(acc[0][j], A02_0.x, A13_0.x, A02_0.y, A13_0.y, B.x, B.y);
                mma8(acc[1][j], A02_1.x, A13_1.x, A02_1.y, A13_1.y, B.x, B.y);
            }
        }

        if (c + 1 < 32)
            proj_sts(psm + ((c + 1) & 1) * 4096,
                     psm + 8192 + ((c + 1) & 1) * 6144, t, xr, wlo, whi);
        __syncthreads();
    }

    #pragma unroll
    for (int mt = 0; mt < 2; mt++) {
        int r = row0 + warpM * 32 + mt * 16 + g;
        #pragma unroll
        for (int j = 0; j < 6; j++) {
            int nb = warpN * 48 + j * 8;
            float* o = (nb < 64) ? g_q : (nb < 128) ? g_k : g_v;
            int cc = (nb & 63) + 2 * tig;
            *(float2*)&o[(size_t)r * DD + cc] = make_float2(
                __uint_as_float(f2tf(acc[mt][j][0])),
                __uint_as_float(f2tf(acc[mt][j][1])));
            *(float2*)&o[(size_t)(r + 8) * DD + cc] = make_float2(
                __uint_as_float(f2tf(acc[mt][j][2])),
                __uint_as_float(f2tf(acc[mt][j][3])));
        }
    }
}

// ---------------------------------------------------------------------------
// Flash attention, tf32 mma. 256 threads = 2 independent 128-thread groups
// (named barriers). Block owns q-tile pair {p, 31-p}:
//   group0: tile p fully (p+1 iters) + tile (31-p) kt in [16, nB)  -> 17 iters
//   group1: tile (31-p) kt in [0,16)                               -> 16 iters
// tile (31-p) partials merged in-block (flash split-k merge).
// q/k/v in gmem are already tf32-rounded; 1/sqrt(D) folded into Q (exact).
// ---------------------------------------------------------------------------
#define ATTN_SMEM (2 * 16384 * 4)   // per group: qs/ks/vt/ps 4096 words each

__device__ __forceinline__ void run_tile(
    int b, int qt, int kt0, int kt1,
    uint32_t* qs, uint32_t* ks, uint32_t* vt, uint32_t* ps,
    int lt, int barid,
    float& m0r, float& m1r, float& l0r, float& l1r, float o[8][4])
{
    const int lane = lt & 31;
    const int warp = lt >> 5;
    const int g   = lane >> 2;
    const int tig = lane & 3;
    const int wr  = warp * 16;

    groupbar(barid);   // prior smem consumers done before overwriting qs

    const float* qbase = g_q + ((size_t)(b * TT + qt * 64)) * DD;
    #pragma unroll
    for (int i = 0; i < 8; i++) {
        int f4 = lt + i * 128;
        int r = f4 >> 4, c0 = (f4 & 15) * 4;
        float4 v = *(const float4*)&qbase[r * DD + c0];
        qs[swz64(r, perm8(c0 + 0))] = __float_as_uint(v.x * 0.125f);
        qs[swz64(r, perm8(c0 + 1))] = __float_as_uint(v.y * 0.125f);
        qs[swz64(r, perm8(c0 + 2))] = __float_as_uint(v.z * 0.125f);
        qs[swz64(r, perm8(c0 + 3))] = __float_as_uint(v.w * 0.125f);
    }

    float m0 = m0r, m1 = m1r, l0 = l0r, l1 = l1r;

    for (int kt = kt0; kt < kt1; kt++) {
        groupbar(barid);   // prev iter's reads done
        const float* kbase = g_k + ((size_t)(b * TT + kt * 64)) * DD;
        const float* vbase = g_v + ((size_t)(b * TT + kt * 64)) * DD;

        #pragma unroll
        for (int i = 0; i < 8; i++) {
            int f4 = lt + i * 128;
            int r = f4 >> 4, c0 = (f4 & 15) * 4;
            float4 v = *(const float4*)&kbase[r * DD + c0];
            ks[swz64(r, perm8(c0 + 0))] = __float_as_uint(v.x);
            ks[swz64(r, perm8(c0 + 1))] = __float_as_uint(v.y);
            ks[swz64(r, perm8(c0 + 2))] = __float_as_uint(v.z);
            ks[swz64(r, perm8(c0 + 3))] = __float_as_uint(v.w);
        }
        #pragma unroll
        for (int i = 0; i < 4; i++) {
            int tau = lt + i * 128;
            int pc = tau & 31, j = tau >> 5;
            int cc = ((pc >> 2) << 3) | (pc & 3);
            const float* vb = vbase + cc * DD + j * 4;
            float4 lo = *(const float4*)vb;
            float4 hi = *(const float4*)(vb + 4 * DD);
            int col2 = ((cc & ~7) >> 1) | (cc & 3);
            uint2* v2 = (uint2*)vt;
            v2[(4 * j + 0) * 32 + (col2 ^ 0)]  = make_uint2(__float_as_uint(lo.x), __float_as_uint(hi.x));
            v2[(4 * j + 1) * 32 + (col2 ^ 4)]  = make_uint2(__float_as_uint(lo.y), __float_as_uint(hi.y));
            v2[(4 * j + 2) * 32 + (col2 ^ 8)]  = make_uint2(__float_as_uint(lo.z), __float_as_uint(hi.z));
            v2[(4 * j + 3) * 32 + (col2 ^ 12)] = make_uint2(__float_as_uint(lo.w), __float_as_uint(hi.w));
        }
        groupbar(barid);

        // ---- S = Q K^T (scale pre-folded into Q) ----
        float s[8][4];
        #pragma unroll
        for (int nt = 0; nt < 8; nt++)
            #pragma unroll
            for (int e = 0; e < 4; e++) s[nt][e] = 0.f;

        #pragma unroll
        for (int ksx = 0; ksx < 8; ksx++) {
            int c2 = ksx * 4 + tig;
            uint2 A02 = ld64(qs, wr + g,     c2);
            uint2 A13 = ld64(qs, wr + g + 8, c2);
            #pragma unroll
            for (int nt = 0; nt < 8; nt++) {
                uint2 B = ld64(ks, nt * 8 + g, c2);
                mma8(s[nt], A02.x, A13.x, A02.y, A13.y, B.x, B.y);
            }
        }

        // ---- softmax ----
        const bool diag = (kt == qt);
        const int r0 = wr + g, r1 = wr + g + 8;
        float mx0 = -INFINITY, mx1 = -INFINITY;
        #pragma unroll
        for (int nt = 0; nt < 8; nt++) {
            int c0 = nt * 8 + 2 * tig;
            if (diag) {
                if (c0     > r0) s[nt][0] = -INFINITY;
                if (c0 + 1 > r0) s[nt][1] = -INFINITY;
                if (c0     > r1) s[nt][2] = -INFINITY;
                if (c0 + 1 > r1) s[nt][3] = -INFINITY;
            }
            mx0 = fmaxf(mx0, fmaxf(s[nt][0], s[nt][1]));
            mx1 = fmaxf(mx1, fmaxf(s[nt][2], s[nt][3]));
        }
        mx0 = fmaxf(mx0, __shfl_xor_sync(0xffffffffu, mx0, 1));
        mx0 = fmaxf(mx0, __shfl_xor_sync(0xffffffffu, mx0, 2));
        mx1 = fmaxf(mx1, __shfl_xor_sync(0xffffffffu, mx1, 1));
        mx1 = fmaxf(mx1, __shfl_xor_sync(0xffffffffu, mx1, 2));

        float M0 = fmaxf(m0, mx0), M1 = fmaxf(m1, mx1);
        float corr0 = __expf(m0 - M0), corr1 = __expf(m1 - M1);

        float ls0 = 0.f, ls1 = 0.f;
        #pragma unroll
        for (int nt = 0; nt < 8; nt++) {
            int c0 = nt * 8 + 2 * tig;
            float p0 = __expf(s[nt][0] - M0);
            float p1 = __expf(s[nt][1] - M0);
            float p2 = __expf(s[nt][2] - M1);
            float p3 = __expf(s[nt][3] - M1);
            ls0 += p0 + p1; ls1 += p2 + p3;
            ps[swz64(r0, perm8(c0))]     = f2tf(p0);
            ps[swz64(r0, perm8(c0 + 1))] = f2tf(p1);
            ps[swz64(r1, perm8(c0))]     = f2tf(p2);
            ps[swz64(r1, perm8(c0 + 1))] = f2tf(p3);
        }
        ls0 += __shfl_xor_sync(0xffffffffu, ls0, 1);
        ls0 += __shfl_xor_sync(0xffffffffu, ls0, 2);
        ls1 += __shfl_xor_sync(0xffffffffu, ls1, 1);
        ls1 += __shfl_xor_sync(0xffffffffu, ls1, 2);

        l0 = l0 * corr0 + ls0; m0 = M0;
        l1 = l1 * corr1 + ls1; m1 = M1;
        #pragma unroll
        for (int nt = 0; nt < 8; nt++) {
            o[nt][0] *= corr0; o[nt][1] *= corr0;
            o[nt][2] *= corr1; o[nt][3] *= corr1;
        }
        __syncwarp();   // ps is warp-local

        // ---- O += P V ----
        #pragma unroll
        for (int ksx = 0; ksx < 8; ksx++) {
            int c2 = ksx * 4 + tig;
            uint2 A02 = ld64(ps, wr + g,     c2);
            uint2 A13 = ld64(ps, wr + g + 8, c2);
            #pragma unroll
            for (int nt = 0; nt < 8; nt++) {
                uint2 B = ld64(vt, nt * 8 + g, c2);
                mma8(o[nt], A02.x, A13.x, A02.y, A13.y, B.x, B.y);
            }
        }
    }

    m0r = m0; m1r = m1; l0r = l0; l1r = l1;
}

__global__ __launch_bounds__(256) void attn_kernel(float* __restrict__ out)
{
    extern __shared__ uint32_t sm[];
    const int tid   = threadIdx.x;
    const int group = tid >> 7;
    const int lt    = tid & 127;
    const int lane  = tid & 31;
    const int warp  = (tid >> 5) & 3;
    const int g     = lane >> 2;
    const int tig   = lane & 3;
    const int wr    = warp * 16;
    const int b     = blockIdx.x >> 4;
    const int p     = blockIdx.x & 15;
    const int tileA = p, tileB = 31 - p;
    const int nB    = tileB + 1;
    const int barid = group + 1;

    uint32_t* gb = sm + group * 16384;
    uint32_t* qs = gb, *ks = gb + 4096, *vt = gb + 8192, *ps = gb + 12288;

    // merge scratch lives in group0's ks/vt region (free after its loops)
    float* O0  = (float*)(sm + 4096);
    float* msm = (float*)(sm + 8192);
    float* lsm = (float*)(sm + 8192 + 64);

    float m0, m1, l0, l1, o[8][4];
    const int r0 = wr + g, r1 = wr + g + 8;

    if (group == 0) {
        // --- tile A, full range ---
        m0 = m1 = -INFINITY; l0 = l1 = 0.f;
        #pragma unroll
        for (int nt = 0; nt < 8; nt++)
            #pragma unroll
            for (int e = 0; e < 4; e++) o[nt][e] = 0.f;
        run_tile(b, tileA, 0, tileA + 1, qs, ks, vt, ps, lt, barid, m0, m1, l0, l1, o);

        const float iv0 = 1.f / l0, iv1 = 1.f / l1;
        float* ob = out + ((size_t)(b * TT + tileA * 64)) * DD;
        #pragma unroll
        for (int nt = 0; nt < 8; nt++) {
            int cc = nt * 8 + 2 * tig;
            *(float2*)&ob[r0 * DD + cc] = make_float2(o[nt][0] * iv0, o[nt][1] * iv0);
            *(float2*)&ob[r1 * DD + cc] = make_float2(o[nt][2] * iv1, o[nt][3] * iv1);
        }

        // --- tile B tail: kt in [16, nB) ---
        m0 = m1 = -INFINITY; l0 = l1 = 0.f;
        #pragma unroll
        for (int nt = 0; nt < 8; nt++)
            #pragma unroll
            for (int e = 0; e < 4; e++) o[nt][e] = 0.f;
        run_tile(b, tileB, 16, nB, qs, ks, vt, ps, lt, barid, m0, m1, l0, l1, o);

        groupbar(barid);   // all group0 warps done reading ks/vt before reuse
        #pragma unroll
        for (int nt = 0; nt < 8; nt++) {
            int cc = nt * 8 + 2 * tig;
            O0[r0 * 64 + cc]     = o[nt][0];
            O0[r0 * 64 + cc + 1] = o[nt][1];
            O0[r1 * 64 + cc]     = o[nt][2];
            O0[r1 * 64 + cc + 1] = o[nt][3];
        }
        if (tig == 0) {
            msm[r0] = m0; lsm[r0] = l0;
            msm[r1] = m1; lsm[r1] = l1;
        }
    } else {
        // --- tile B head: kt in [0, 16) ---
        m0 = m1 = -INFINITY; l0 = l1 = 0.f;
        #pragma unroll
        for (int nt = 0; nt < 8; nt++)
            #pragma unroll
            for (int e = 0; e < 4; e++) o[nt][e] = 0.f;
        run_tile(b, tileB, 0, 16, qs, ks, vt, ps, lt, barid, m0, m1, l0, l1, o);
    }

    __syncthreads();   // both groups arrive exactly once

    if (group == 1) {
        // merge own partial (head) with group0's partial (tail) and write tile B
        float Ma = fmaxf(m0, msm[r0]);
        float e1a = __expf(m0 - Ma), e0a = __expf(msm[r0] - Ma);
        float iva = 1.f / (l0 * e1a + lsm[r0] * e0a);
        float Mb = fmaxf(m1, msm[r1]);
        float e1b = __expf(m1 - Mb), e0b = __expf(msm[r1] - Mb);
        float ivb = 1.f / (l1 * e1b + lsm[r1] * e0b);

        float* ob = out + ((size_t)(b * TT + tileB * 64)) * DD;
        #pragma unroll
        for (int nt = 0; nt < 8; nt++) {
            int cc = nt * 8 + 2 * tig;
            float fa0 = (o[nt][0] * e1a + O0[r0 * 64 + cc]     * e0a) * iva;
            float fa1 = (o[nt][1] * e1a + O0[r0 * 64 + cc + 1] * e0a) * iva;
            float fb0 = (o[nt][2] * e1b + O0[r1 * 64 + cc]     * e0b) * ivb;
            float fb1 = (o[nt][3] * e1b + O0[r1 * 64 + cc + 1] * e0b) * ivb;
            *(float2*)&ob[r0 * DD + cc] = make_float2(fa0, fa1);
            *(float2*)&ob[r1 * DD + cc] = make_float2(fb0, fb1);
        }
    }
}

// ---------------------------------------------------------------------------
extern "C" void kernel_launch(void* const* d_in, const int* in_sizes, int n_in,
                              void* d_out, int out_size)
{
    const float* x  = (const float*)d_in[0];
    const float* Wk = (const float*)d_in[1];
    const float* Wq = (const float*)d_in[2];
    const float* Wv = (const float*)d_in[3];
    float* out = (float*)d_out;

    cudaFuncSetAttribute(proj_kernel,
                         cudaFuncAttributeMaxDynamicSharedMemorySize, PROJ_SMEM);
    cudaFuncSetAttribute(attn_kernel,
                         cudaFuncAttributeMaxDynamicSharedMemorySize, ATTN_SMEM);

    proj_kernel<<<NTOK / 128, 512, PROJ_SMEM>>>(x, Wk, Wq, Wv);
    attn_kernel<<<BB * 16, 256, ATTN_SMEM>>>(out);
}